// round 1
// baseline (speedup 1.0000x reference)
#include <cuda_runtime.h>
#include <cstdint>

#define T_STEPS 2048
#define B_SZ    16
#define D_SZ    1024
#define BD      (B_SZ*D_SZ)          /* 16384 */
#define NCTA    128
#define NTHR    256
#define HPITCH  1028                 /* 1024 + 4 floats pad: rows shift 4 banks */

// 128 MB scratch for the precomputed input projection (allowed: __device__ global)
__device__ float    g_xp[(size_t)T_STEPS * BD];
__device__ unsigned g_bar;

// ---------------- packed fp32x2 helpers (sm_100+ PTX) ----------------
__device__ __forceinline__ void ffma2(unsigned long long &d,
                                      unsigned long long a,
                                      unsigned long long b) {
    asm("fma.rn.f32x2 %0, %1, %2, %0;" : "+l"(d) : "l"(a), "l"(b));
}
__device__ __forceinline__ unsigned long long dup2(float a) {
    unsigned long long r;
    asm("mov.b64 %0, {%1, %1};" : "=l"(r) : "f"(a));
    return r;
}
__device__ __forceinline__ float2 unpack2(unsigned long long v) {
    float2 r;
    asm("mov.b64 {%0, %1}, %2;" : "=f"(r.x), "=f"(r.y) : "l"(v));
    return r;
}

__global__ void init_kernel() { g_bar = 0u; }

// ---------------------------------------------------------------------
// Kernel 1: xp[m,e] = sum_d x[m,d]*Wx[e,d] + b[e]   (M=32768, N=K=1024)
// 64x64 tile, BK=16, 256 threads, 4x4 micro-tile, f32x2 FMAs.
// ---------------------------------------------------------------------
__global__ __launch_bounds__(256) void xp_gemm_kernel(
    const float* __restrict__ X,
    const float* __restrict__ Wx,
    const float* __restrict__ bias)
{
    __shared__ __align__(16) float As[16][68];   // [k][m]
    __shared__ __align__(16) float Bs[16][68];   // [k][n]

    const int tid   = threadIdx.x;
    const int mBase = blockIdx.y * 64;
    const int nBase = blockIdx.x * 64;

    const int lrow = tid >> 2;          // 0..63
    const int lk4  = (tid & 3) << 2;    // 0,4,8,12

    const int ty = tid >> 4;            // 0..15 -> m group
    const int tx = tid & 15;            // 0..15 -> n group

    unsigned long long acc[4][2];
#pragma unroll
    for (int i = 0; i < 4; i++) { acc[i][0] = 0ull; acc[i][1] = 0ull; }

    for (int k0 = 0; k0 < 1024; k0 += 16) {
        float4 av = *reinterpret_cast<const float4*>(
            &X[(size_t)(mBase + lrow) * 1024 + k0 + lk4]);
        float4 bv = *reinterpret_cast<const float4*>(
            &Wx[(size_t)(nBase + lrow) * 1024 + k0 + lk4]);
        As[lk4 + 0][lrow] = av.x; As[lk4 + 1][lrow] = av.y;
        As[lk4 + 2][lrow] = av.z; As[lk4 + 3][lrow] = av.w;
        Bs[lk4 + 0][lrow] = bv.x; Bs[lk4 + 1][lrow] = bv.y;
        Bs[lk4 + 2][lrow] = bv.z; Bs[lk4 + 3][lrow] = bv.w;
        __syncthreads();

#pragma unroll
        for (int k = 0; k < 16; k++) {
            float4 a = *reinterpret_cast<const float4*>(&As[k][ty << 2]);
            ulonglong2 bp = *reinterpret_cast<const ulonglong2*>(&Bs[k][tx << 2]);
            unsigned long long a0 = dup2(a.x), a1 = dup2(a.y);
            unsigned long long a2 = dup2(a.z), a3 = dup2(a.w);
            ffma2(acc[0][0], a0, bp.x); ffma2(acc[0][1], a0, bp.y);
            ffma2(acc[1][0], a1, bp.x); ffma2(acc[1][1], a1, bp.y);
            ffma2(acc[2][0], a2, bp.x); ffma2(acc[2][1], a2, bp.y);
            ffma2(acc[3][0], a3, bp.x); ffma2(acc[3][1], a3, bp.y);
        }
        __syncthreads();
    }

    const int col = nBase + (tx << 2);
    const float4 bv = *reinterpret_cast<const float4*>(&bias[col]);
#pragma unroll
    for (int m = 0; m < 4; m++) {
        const int row = mBase + (ty << 2) + m;
        float2 c01 = unpack2(acc[m][0]);
        float2 c23 = unpack2(acc[m][1]);
        float4 r;
        r.x = c01.x + bv.x; r.y = c01.y + bv.y;
        r.z = c23.x + bv.z; r.w = c23.y + bv.w;
        *reinterpret_cast<float4*>(&g_xp[(size_t)row * 1024 + col]) = r;
    }
}

// ---------------------------------------------------------------------
// Kernel 2: persistent recurrence. 128 CTAs x 256 threads.
// CTA c owns output columns [c*8, c*8+8); its 8 rows of W_h live in SMEM.
// Each step: broadcast-load h[t] (64KB) into SMEM, dot-products with
// f32x2 FMAs (K split between thread halves), tanh/silu epilogue,
// store h[t+1] + out[t], then a chip-wide sense barrier.
// ---------------------------------------------------------------------
__device__ __forceinline__ unsigned ld_vol(const unsigned* p) {
    return *(volatile const unsigned*)p;
}

__global__ __launch_bounds__(256) void recur_kernel(
    const float* __restrict__ Z,
    const float* __restrict__ H0,
    const float* __restrict__ Wh,
    const float* __restrict__ Gz,
    const float* __restrict__ Gh,
    const float* __restrict__ Bg,
    float* __restrict__ Out,
    float* __restrict__ Hout)
{
    extern __shared__ __align__(16) float sm[];
    float* w_s = sm;                   // 8  * HPITCH
    float* h_s = sm + 8 * HPITCH;      // 16 * HPITCH
    float* red = sm + 24 * HPITCH;     // 128

    const int tid   = threadIdx.x;
    const int cta   = blockIdx.x;
    const int ncol0 = cta * 8;

    // Preload this CTA's 8 rows of W_h into SMEM (stays for all 2048 steps).
#pragma unroll 4
    for (int c4 = tid; c4 < 8 * 256; c4 += NTHR) {
        const int n  = c4 >> 8;
        const int k4 = (c4 & 255) << 2;
        float4 v = *reinterpret_cast<const float4*>(
            &Wh[(size_t)(ncol0 + n) * 1024 + k4]);
        *reinterpret_cast<float4*>(&w_s[n * HPITCH + k4]) = v;
    }

    const int p    = tid & 127;   // output index within CTA
    const int half = tid >> 7;    // K-split half
    const int b    = p >> 3;      // batch row 0..15
    const int n    = p & 7;       // local column 0..7
    const int gcol = ncol0 + n;

    // h[0] = h0 (also part of the required output)
    if (half == 0)
        Hout[(size_t)b * 1024 + gcol] = H0[(size_t)b * 1024 + gcol];

    const float gz_r = Gz[gcol];
    const float gh_r = Gh[gcol];
    const float bg_r = Bg[gcol];

    const float* wrow = &w_s[n * HPITCH + half * 512];
    const float* hrow = &h_s[b * HPITCH + half * 512];

    for (int t = 0; t < T_STEPS; ++t) {
        // ---- broadcast-load h[t] (fresh addresses each step; .cg = L2) ----
        const float* hsrc = (t == 0) ? H0 : (Hout + (size_t)t * BD);
#pragma unroll
        for (int c4 = tid; c4 < 16 * 256; c4 += NTHR) {
            const int bb = c4 >> 8;
            const int k4 = (c4 & 255) << 2;
            float4 v = __ldcg(reinterpret_cast<const float4*>(
                &hsrc[(size_t)bb * 1024 + k4]));
            *reinterpret_cast<float4*>(&h_s[bb * HPITCH + k4]) = v;
        }
        __syncthreads();

        // ---- dot product: 512 MACs per thread, 4 packed accumulators ----
        unsigned long long acc0 = 0ull, acc1 = 0ull, acc2 = 0ull, acc3 = 0ull;
#pragma unroll 8
        for (int k = 0; k < 512; k += 8) {
            ulonglong2 hv0 = *reinterpret_cast<const ulonglong2*>(hrow + k);
            ulonglong2 wv0 = *reinterpret_cast<const ulonglong2*>(wrow + k);
            ffma2(acc0, hv0.x, wv0.x);
            ffma2(acc1, hv0.y, wv0.y);
            ulonglong2 hv1 = *reinterpret_cast<const ulonglong2*>(hrow + k + 4);
            ulonglong2 wv1 = *reinterpret_cast<const ulonglong2*>(wrow + k + 4);
            ffma2(acc2, hv1.x, wv1.x);
            ffma2(acc3, hv1.y, wv1.y);
        }
        float2 f0 = unpack2(acc0), f1 = unpack2(acc1);
        float2 f2 = unpack2(acc2), f3 = unpack2(acc3);
        float accs = ((f0.x + f0.y) + (f1.x + f1.y)) +
                     ((f2.x + f2.y) + (f3.x + f3.y));

        if (half) red[p] = accs;
        __syncthreads();

        if (!half) {
            const float  dot = accs + red[p];
            const size_t idx = (size_t)t * BD + (size_t)b * 1024 + gcol;
            const float  xpv = g_xp[idx];
            const float  hn  = tanhf(xpv + dot);
            const float  zv  = Z[idx];
            const float  pre = zv * gz_r + hn * gh_r + bg_r;
            const float  sg  = 1.0f / (1.0f + __expf(-pre));
            Out[idx] = hn * (pre * sg);
            Hout[(size_t)(t + 1) * BD + (size_t)b * 1024 + gcol] = hn;
        }
        __syncthreads();   // all stores issued before the fence below

        // ---- chip-wide barrier (fence / arrive / spin / fence) ----
        if (tid == 0) {
            __threadfence();
            atomicAdd(&g_bar, 1u);
            const unsigned target = (unsigned)gridDim.x * (unsigned)(t + 1);
            while (ld_vol(&g_bar) < target) { }
            __threadfence();
        }
        __syncthreads();   // release CTA; also protects h_s reuse next step
    }
}

// ---------------------------------------------------------------------
extern "C" void kernel_launch(void* const* d_in, const int* in_sizes, int n_in,
                              void* d_out, int out_size)
{
    const float* x  = (const float*)d_in[0];
    const float* z  = (const float*)d_in[1];
    const float* h0 = (const float*)d_in[2];
    const float* Wx = (const float*)d_in[3];
    const float* Wh = (const float*)d_in[4];
    const float* b  = (const float*)d_in[5];
    const float* gz = (const float*)d_in[6];
    const float* gh = (const float*)d_in[7];
    const float* bg = (const float*)d_in[8];

    float* out  = (float*)d_out;                       // [T,B,D]
    float* hout = out + (size_t)T_STEPS * BD;          // [T+1,B,D]

    init_kernel<<<1, 1>>>();

    dim3 gGemm(1024 / 64, (T_STEPS * B_SZ) / 64);      // (16, 512)
    xp_gemm_kernel<<<gGemm, 256>>>(x, Wx, b);

    const int smem_bytes = (24 * HPITCH + 128) * (int)sizeof(float);  // 99200
    cudaFuncSetAttribute(recur_kernel,
                         cudaFuncAttributeMaxDynamicSharedMemorySize, smem_bytes);
    recur_kernel<<<NCTA, NTHR, smem_bytes>>>(z, h0, Wh, gz, gh, bg, out, hout);
}

// round 2
// speedup vs baseline: 1.0018x; 1.0018x over previous
#include <cuda_runtime.h>
#include <cstdint>

#define T_STEPS 2048
#define B_SZ    16
#define D_SZ    1024
#define BD      (B_SZ*D_SZ)          /* 16384 */
#define NCTA    128
#define NTHR    256
#define HPITCH  1028                 /* 1024 + 4 floats pad: rows shift 4 banks */

// 128 MB scratch for the precomputed input projection (allowed: __device__ global)
__device__ float    g_xp[(size_t)T_STEPS * BD];
__device__ unsigned g_bar;

// ---------------- packed fp32x2 helpers (sm_100+ PTX) ----------------
__device__ __forceinline__ void ffma2(unsigned long long &d,
                                      unsigned long long a,
                                      unsigned long long b) {
    asm("fma.rn.f32x2 %0, %1, %2, %0;" : "+l"(d) : "l"(a), "l"(b));
}
__device__ __forceinline__ unsigned long long dup2(float a) {
    unsigned long long r;
    asm("mov.b64 %0, {%1, %1};" : "=l"(r) : "f"(a));
    return r;
}
__device__ __forceinline__ float2 unpack2(unsigned long long v) {
    float2 r;
    asm("mov.b64 {%0, %1}, %2;" : "=f"(r.x), "=f"(r.y) : "l"(v));
    return r;
}

__global__ void init_kernel() { g_bar = 0u; }

// ---------------------------------------------------------------------
// Kernel 1: xp[m,e] = sum_d x[m,d]*Wx[e,d] + b[e]   (M=32768, N=K=1024)
// 64x64 tile, BK=16, 256 threads, 4x4 micro-tile, f32x2 FMAs.
// ---------------------------------------------------------------------
__global__ __launch_bounds__(256) void xp_gemm_kernel(
    const float* __restrict__ X,
    const float* __restrict__ Wx,
    const float* __restrict__ bias)
{
    __shared__ __align__(16) float As[16][68];   // [k][m]
    __shared__ __align__(16) float Bs[16][68];   // [k][n]

    const int tid   = threadIdx.x;
    const int mBase = blockIdx.y * 64;
    const int nBase = blockIdx.x * 64;

    const int lrow = tid >> 2;          // 0..63
    const int lk4  = (tid & 3) << 2;    // 0,4,8,12

    const int ty = tid >> 4;            // 0..15 -> m group
    const int tx = tid & 15;            // 0..15 -> n group

    unsigned long long acc[4][2];
#pragma unroll
    for (int i = 0; i < 4; i++) { acc[i][0] = 0ull; acc[i][1] = 0ull; }

    for (int k0 = 0; k0 < 1024; k0 += 16) {
        float4 av = *reinterpret_cast<const float4*>(
            &X[(size_t)(mBase + lrow) * 1024 + k0 + lk4]);
        float4 bv = *reinterpret_cast<const float4*>(
            &Wx[(size_t)(nBase + lrow) * 1024 + k0 + lk4]);
        As[lk4 + 0][lrow] = av.x; As[lk4 + 1][lrow] = av.y;
        As[lk4 + 2][lrow] = av.z; As[lk4 + 3][lrow] = av.w;
        Bs[lk4 + 0][lrow] = bv.x; Bs[lk4 + 1][lrow] = bv.y;
        Bs[lk4 + 2][lrow] = bv.z; Bs[lk4 + 3][lrow] = bv.w;
        __syncthreads();

#pragma unroll
        for (int k = 0; k < 16; k++) {
            float4 a = *reinterpret_cast<const float4*>(&As[k][ty << 2]);
            ulonglong2 bp = *reinterpret_cast<const ulonglong2*>(&Bs[k][tx << 2]);
            unsigned long long a0 = dup2(a.x), a1 = dup2(a.y);
            unsigned long long a2 = dup2(a.z), a3 = dup2(a.w);
            ffma2(acc[0][0], a0, bp.x); ffma2(acc[0][1], a0, bp.y);
            ffma2(acc[1][0], a1, bp.x); ffma2(acc[1][1], a1, bp.y);
            ffma2(acc[2][0], a2, bp.x); ffma2(acc[2][1], a2, bp.y);
            ffma2(acc[3][0], a3, bp.x); ffma2(acc[3][1], a3, bp.y);
        }
        __syncthreads();
    }

    const int col = nBase + (tx << 2);
    const float4 bv = *reinterpret_cast<const float4*>(&bias[col]);
#pragma unroll
    for (int m = 0; m < 4; m++) {
        const int row = mBase + (ty << 2) + m;
        float2 c01 = unpack2(acc[m][0]);
        float2 c23 = unpack2(acc[m][1]);
        float4 r;
        r.x = c01.x + bv.x; r.y = c01.y + bv.y;
        r.z = c23.x + bv.z; r.w = c23.y + bv.w;
        *reinterpret_cast<float4*>(&g_xp[(size_t)row * 1024 + col]) = r;
    }
}

// ---------------------------------------------------------------------
// Kernel 2: persistent recurrence. 128 CTAs x 256 threads.
// CTA c owns output columns [c*8, c*8+8); its 8 rows of W_h live in SMEM.
// Each step: broadcast-load h[t] (64KB) into SMEM, dot-products with
// f32x2 FMAs (K split between thread halves), tanh/silu epilogue,
// store h[t+1] + out[t], then a chip-wide sense barrier.
// ---------------------------------------------------------------------
__device__ __forceinline__ unsigned ld_vol(const unsigned* p) {
    return *(volatile const unsigned*)p;
}

__global__ __launch_bounds__(256) void recur_kernel(
    const float* __restrict__ Z,
    const float* __restrict__ H0,
    const float* __restrict__ Wh,
    const float* __restrict__ Gz,
    const float* __restrict__ Gh,
    const float* __restrict__ Bg,
    float* __restrict__ Out,
    float* __restrict__ Hout)
{
    extern __shared__ __align__(16) float sm[];
    float* w_s = sm;                   // 8  * HPITCH
    float* h_s = sm + 8 * HPITCH;      // 16 * HPITCH
    float* red = sm + 24 * HPITCH;     // 128

    const int tid   = threadIdx.x;
    const int cta   = blockIdx.x;
    const int ncol0 = cta * 8;

    // Preload this CTA's 8 rows of W_h into SMEM (stays for all 2048 steps).
#pragma unroll 4
    for (int c4 = tid; c4 < 8 * 256; c4 += NTHR) {
        const int n  = c4 >> 8;
        const int k4 = (c4 & 255) << 2;
        float4 v = *reinterpret_cast<const float4*>(
            &Wh[(size_t)(ncol0 + n) * 1024 + k4]);
        *reinterpret_cast<float4*>(&w_s[n * HPITCH + k4]) = v;
    }

    const int p    = tid & 127;   // output index within CTA
    const int half = tid >> 7;    // K-split half
    const int b    = p >> 3;      // batch row 0..15
    const int n    = p & 7;       // local column 0..7
    const int gcol = ncol0 + n;

    // h[0] = h0 (also part of the required output)
    if (half == 0)
        Hout[(size_t)b * 1024 + gcol] = H0[(size_t)b * 1024 + gcol];

    const float gz_r = Gz[gcol];
    const float gh_r = Gh[gcol];
    const float bg_r = Bg[gcol];

    const float* wrow = &w_s[n * HPITCH + half * 512];
    const float* hrow = &h_s[b * HPITCH + half * 512];

    for (int t = 0; t < T_STEPS; ++t) {
        // ---- broadcast-load h[t] (fresh addresses each step; .cg = L2) ----
        const float* hsrc = (t == 0) ? H0 : (Hout + (size_t)t * BD);
#pragma unroll
        for (int c4 = tid; c4 < 16 * 256; c4 += NTHR) {
            const int bb = c4 >> 8;
            const int k4 = (c4 & 255) << 2;
            float4 v = __ldcg(reinterpret_cast<const float4*>(
                &hsrc[(size_t)bb * 1024 + k4]));
            *reinterpret_cast<float4*>(&h_s[bb * HPITCH + k4]) = v;
        }
        __syncthreads();

        // ---- dot product: 512 MACs per thread, 4 packed accumulators ----
        unsigned long long acc0 = 0ull, acc1 = 0ull, acc2 = 0ull, acc3 = 0ull;
#pragma unroll 8
        for (int k = 0; k < 512; k += 8) {
            ulonglong2 hv0 = *reinterpret_cast<const ulonglong2*>(hrow + k);
            ulonglong2 wv0 = *reinterpret_cast<const ulonglong2*>(wrow + k);
            ffma2(acc0, hv0.x, wv0.x);
            ffma2(acc1, hv0.y, wv0.y);
            ulonglong2 hv1 = *reinterpret_cast<const ulonglong2*>(hrow + k + 4);
            ulonglong2 wv1 = *reinterpret_cast<const ulonglong2*>(wrow + k + 4);
            ffma2(acc2, hv1.x, wv1.x);
            ffma2(acc3, hv1.y, wv1.y);
        }
        float2 f0 = unpack2(acc0), f1 = unpack2(acc1);
        float2 f2 = unpack2(acc2), f3 = unpack2(acc3);
        float accs = ((f0.x + f0.y) + (f1.x + f1.y)) +
                     ((f2.x + f2.y) + (f3.x + f3.y));

        if (half) red[p] = accs;
        __syncthreads();

        if (!half) {
            const float  dot = accs + red[p];
            const size_t idx = (size_t)t * BD + (size_t)b * 1024 + gcol;
            const float  xpv = g_xp[idx];
            const float  hn  = tanhf(xpv + dot);
            const float  zv  = Z[idx];
            const float  pre = zv * gz_r + hn * gh_r + bg_r;
            const float  sg  = 1.0f / (1.0f + __expf(-pre));
            Out[idx] = hn * (pre * sg);
            Hout[(size_t)(t + 1) * BD + (size_t)b * 1024 + gcol] = hn;
        }
        __syncthreads();   // all stores issued before the fence below

        // ---- chip-wide barrier (fence / arrive / spin / fence) ----
        if (tid == 0) {
            __threadfence();
            atomicAdd(&g_bar, 1u);
            const unsigned target = (unsigned)gridDim.x * (unsigned)(t + 1);
            while (ld_vol(&g_bar) < target) { }
            __threadfence();
        }
        __syncthreads();   // release CTA; also protects h_s reuse next step
    }
}

// ---------------------------------------------------------------------
extern "C" void kernel_launch(void* const* d_in, const int* in_sizes, int n_in,
                              void* d_out, int out_size)
{
    const float* x  = (const float*)d_in[0];
    const float* z  = (const float*)d_in[1];
    const float* h0 = (const float*)d_in[2];
    const float* Wx = (const float*)d_in[3];
    const float* Wh = (const float*)d_in[4];
    const float* b  = (const float*)d_in[5];
    const float* gz = (const float*)d_in[6];
    const float* gh = (const float*)d_in[7];
    const float* bg = (const float*)d_in[8];

    float* out  = (float*)d_out;                       // [T,B,D]
    float* hout = out + (size_t)T_STEPS * BD;          // [T+1,B,D]

    init_kernel<<<1, 1>>>();

    dim3 gGemm(1024 / 64, (T_STEPS * B_SZ) / 64);      // (16, 512)
    xp_gemm_kernel<<<gGemm, 256>>>(x, Wx, b);

    const int smem_bytes = (24 * HPITCH + 128) * (int)sizeof(float);  // 99200
    cudaFuncSetAttribute(recur_kernel,
                         cudaFuncAttributeMaxDynamicSharedMemorySize, smem_bytes);
    recur_kernel<<<NCTA, NTHR, smem_bytes>>>(z, h0, Wh, gz, gh, bg, out, hout);
}

// round 3
// speedup vs baseline: 1.6300x; 1.6271x over previous
#include <cuda_runtime.h>
#include <cstdint>

#define T_STEPS 2048
#define B_SZ    16
#define D_SZ    1024
#define BD      (B_SZ*D_SZ)          /* 16384 */
#define NCTA    128
#define NTHR    256
#define HP      1152                 /* h_s row pitch: 1024 + 4 pad per 32 floats */
#define RP      20                   /* reduce buffer pitch (16 + 4) */

// 128 MB scratch for the precomputed input projection (allowed: __device__ global)
__device__ float    g_xp[(size_t)T_STEPS * BD];
__device__ unsigned g_bar;

// ---------------- packed fp32x2 helpers (sm_100+ PTX) ----------------
__device__ __forceinline__ void ffma2(unsigned long long &d,
                                      unsigned long long a,
                                      unsigned long long b) {
    asm("fma.rn.f32x2 %0, %1, %2, %0;" : "+l"(d) : "l"(a), "l"(b));
}
__device__ __forceinline__ unsigned long long dup2(float a) {
    unsigned long long r;
    asm("mov.b64 %0, {%1, %1};" : "=l"(r) : "f"(a));
    return r;
}
__device__ __forceinline__ float2 unpack2(unsigned long long v) {
    float2 r;
    asm("mov.b64 {%0, %1}, %2;" : "=f"(r.x), "=f"(r.y) : "l"(v));
    return r;
}
__device__ __forceinline__ void cp16(uint32_t dst_smem, const void* src) {
    asm volatile("cp.async.cg.shared.global [%0], [%1], 16;"
                 :: "r"(dst_smem), "l"(src) : "memory");
}
__device__ __forceinline__ unsigned ld_vol(const unsigned* p) {
    return *(volatile const unsigned*)p;
}

__global__ void init_kernel() { g_bar = 0u; }

// ---------------------------------------------------------------------
// Kernel 1: xp[m,e] = sum_d x[m,d]*Wx[e,d] + b[e]   (M=32768, N=K=1024)
// (unchanged from R1 — working, revisit after recurrence is fixed)
// ---------------------------------------------------------------------
__global__ __launch_bounds__(256) void xp_gemm_kernel(
    const float* __restrict__ X,
    const float* __restrict__ Wx,
    const float* __restrict__ bias)
{
    __shared__ __align__(16) float As[16][68];
    __shared__ __align__(16) float Bs[16][68];

    const int tid   = threadIdx.x;
    const int mBase = blockIdx.y * 64;
    const int nBase = blockIdx.x * 64;

    const int lrow = tid >> 2;
    const int lk4  = (tid & 3) << 2;
    const int ty = tid >> 4;
    const int tx = tid & 15;

    unsigned long long acc[4][2];
#pragma unroll
    for (int i = 0; i < 4; i++) { acc[i][0] = 0ull; acc[i][1] = 0ull; }

    for (int k0 = 0; k0 < 1024; k0 += 16) {
        float4 av = *reinterpret_cast<const float4*>(
            &X[(size_t)(mBase + lrow) * 1024 + k0 + lk4]);
        float4 bv = *reinterpret_cast<const float4*>(
            &Wx[(size_t)(nBase + lrow) * 1024 + k0 + lk4]);
        As[lk4 + 0][lrow] = av.x; As[lk4 + 1][lrow] = av.y;
        As[lk4 + 2][lrow] = av.z; As[lk4 + 3][lrow] = av.w;
        Bs[lk4 + 0][lrow] = bv.x; Bs[lk4 + 1][lrow] = bv.y;
        Bs[lk4 + 2][lrow] = bv.z; Bs[lk4 + 3][lrow] = bv.w;
        __syncthreads();

#pragma unroll
        for (int k = 0; k < 16; k++) {
            float4 a = *reinterpret_cast<const float4*>(&As[k][ty << 2]);
            ulonglong2 bp = *reinterpret_cast<const ulonglong2*>(&Bs[k][tx << 2]);
            unsigned long long a0 = dup2(a.x), a1 = dup2(a.y);
            unsigned long long a2 = dup2(a.z), a3 = dup2(a.w);
            ffma2(acc[0][0], a0, bp.x); ffma2(acc[0][1], a0, bp.y);
            ffma2(acc[1][0], a1, bp.x); ffma2(acc[1][1], a1, bp.y);
            ffma2(acc[2][0], a2, bp.x); ffma2(acc[2][1], a2, bp.y);
            ffma2(acc[3][0], a3, bp.x); ffma2(acc[3][1], a3, bp.y);
        }
        __syncthreads();
    }

    const int col = nBase + (tx << 2);
    const float4 bv = *reinterpret_cast<const float4*>(&bias[col]);
#pragma unroll
    for (int m = 0; m < 4; m++) {
        const int row = mBase + (ty << 2) + m;
        float2 c01 = unpack2(acc[m][0]);
        float2 c23 = unpack2(acc[m][1]);
        float4 r;
        r.x = c01.x + bv.x; r.y = c01.y + bv.y;
        r.z = c23.x + bv.z; r.w = c23.y + bv.w;
        *reinterpret_cast<float4*>(&g_xp[(size_t)row * 1024 + col]) = r;
    }
}

// ---------------------------------------------------------------------
// Kernel 2: persistent recurrence, register-resident W_h.
// 128 CTAs x 256 threads (8 warps). CTA owns 8 columns.
// Warp w owns k-slice [w*128, w*128+128). Lane: n = lane&7 (column),
// g = lane>>3 (k-subslice of 32). Thread keeps its 32 W_h floats in regs
// for all 2048 steps. h[t] staged via cp.async in 2 groups (overlap);
// compute loads h via broadcast LDS.128 (8-way lane share, pad -> no
// bank conflicts). K-partials reduced through padded SMEM buffer.
// ---------------------------------------------------------------------
__global__ __launch_bounds__(256, 1) void recur_kernel(
    const float* __restrict__ Z,
    const float* __restrict__ H0,
    const float* __restrict__ Wh,
    const float* __restrict__ Gz,
    const float* __restrict__ Gh,
    const float* __restrict__ Bg,
    float* __restrict__ Out,
    float* __restrict__ Hout)
{
    extern __shared__ __align__(16) float sm[];
    float* h_s = sm;                  // 16 * HP floats (padded h tile)
    float* red = sm + 16 * HP;        // 256 * RP floats (reduce buffer)

    const int tid  = threadIdx.x;
    const int warp = tid >> 5;
    const int lane = tid & 31;
    const int cta  = blockIdx.x;

    const int n    = lane & 7;        // column within CTA
    const int g    = lane >> 3;       // k-subgroup 0..3
    const int gcol = cta * 8 + n;
    const int kbase = warp * 128 + g * 32;

    // ---- W_h slice -> registers, resident for all steps ----
    unsigned long long wreg[16];
    {
        const float* wp = Wh + (size_t)gcol * 1024 + kbase;
#pragma unroll
        for (int i = 0; i < 8; i++) {
            ulonglong2 v = *reinterpret_cast<const ulonglong2*>(wp + i * 4);
            wreg[2 * i]     = v.x;
            wreg[2 * i + 1] = v.y;
        }
    }

    // ---- epilogue role (threads 0..127): one output (b,n) each ----
    const int eb = tid >> 3;
    const int en = tid & 7;
    const int egcol = cta * 8 + en;
    float gz_r = 0.f, gh_r = 0.f, bg_r = 0.f;
    if (tid < 128) {
        gz_r = Gz[egcol]; gh_r = Gh[egcol]; bg_r = Bg[egcol];
        // h[0] = h0 (part of required output)
        Hout[(size_t)eb * 1024 + egcol] = H0[(size_t)eb * 1024 + egcol];
    }

    // staging dst offset (words, within a b-row): padded layout
    const int stoff = warp * 144 + lane * 4 + 4 * (lane >> 3);
    const uint32_t h_s_sh = (uint32_t)__cvta_generic_to_shared(h_s);
    // compute-side base: h_s + b*HP + warp*144 + g*36 + i*4
    const float* crow = h_s + warp * 144 + g * 36;
    const int part = (warp * 4 + g) * 8 + n;   // 0..255

    for (int t = 0; t < T_STEPS; ++t) {
        const float* hsrc = (t == 0) ? H0 : (Hout + (size_t)t * BD);

        // ---- prefetch epilogue operands (hidden behind compute) ----
        float xpv = 0.f, zv = 0.f;
        size_t eidx = 0;
        if (tid < 128) {
            eidx = (size_t)t * BD + (size_t)eb * 1024 + egcol;
            xpv = __ldcg(&g_xp[eidx]);
            zv  = __ldcg(&Z[eidx]);
        }

        // ---- stage h[t] slice for this warp, 2 groups for overlap ----
        const float* gsrc = hsrc + warp * 128 + lane * 4;
#pragma unroll
        for (int b = 0; b < 8; b++)
            cp16(h_s_sh + (uint32_t)(b * HP + stoff) * 4u, gsrc + b * 1024);
        asm volatile("cp.async.commit_group;" ::: "memory");
#pragma unroll
        for (int b = 8; b < 16; b++)
            cp16(h_s_sh + (uint32_t)(b * HP + stoff) * 4u, gsrc + b * 1024);
        asm volatile("cp.async.commit_group;" ::: "memory");

        unsigned long long accA[16], accB[16];
#pragma unroll
        for (int b = 0; b < 16; b++) { accA[b] = 0ull; accB[b] = 0ull; }

        // ---- compute half 1 (b=0..7) while half 2 still loading ----
        asm volatile("cp.async.wait_group 1;" ::: "memory");
        __syncwarp();
#pragma unroll
        for (int i = 0; i < 8; i++) {
#pragma unroll
            for (int b = 0; b < 8; b++) {
                ulonglong2 hv = *reinterpret_cast<const ulonglong2*>(
                    crow + b * HP + i * 4);
                ffma2(accA[b], hv.x, wreg[2 * i]);
                ffma2(accB[b], hv.y, wreg[2 * i + 1]);
            }
        }
        // ---- compute half 2 ----
        asm volatile("cp.async.wait_group 0;" ::: "memory");
        __syncwarp();
#pragma unroll
        for (int i = 0; i < 8; i++) {
#pragma unroll
            for (int b = 8; b < 16; b++) {
                ulonglong2 hv = *reinterpret_cast<const ulonglong2*>(
                    crow + b * HP + i * 4);
                ffma2(accA[b], hv.x, wreg[2 * i]);
                ffma2(accB[b], hv.y, wreg[2 * i + 1]);
            }
        }

        // ---- pack partials, write to reduce buffer ----
        float s[16];
#pragma unroll
        for (int b = 0; b < 16; b++) {
            float2 a = unpack2(accA[b]);
            float2 c = unpack2(accB[b]);
            s[b] = (a.x + a.y) + (c.x + c.y);
        }
        {
            float* rp = red + part * RP;
            *reinterpret_cast<float4*>(rp + 0)  = make_float4(s[0],  s[1],  s[2],  s[3]);
            *reinterpret_cast<float4*>(rp + 4)  = make_float4(s[4],  s[5],  s[6],  s[7]);
            *reinterpret_cast<float4*>(rp + 8)  = make_float4(s[8],  s[9],  s[10], s[11]);
            *reinterpret_cast<float4*>(rp + 12) = make_float4(s[12], s[13], s[14], s[15]);
        }
        __syncthreads();

        // ---- final reduce + epilogue (threads 0..127) ----
        if (tid < 128) {
            float dot = 0.f;
#pragma unroll
            for (int m = 0; m < 32; m++)
                dot += red[(en + 8 * m) * RP + eb];

            const float hn  = tanhf(xpv + dot);
            const float pre = zv * gz_r + hn * gh_r + bg_r;
            const float sg  = 1.0f / (1.0f + __expf(-pre));
            Out[eidx] = hn * (pre * sg);
            Hout[(size_t)(t + 1) * BD + (size_t)eb * 1024 + egcol] = hn;
        }
        __syncthreads();   // all stores issued; red safe to rewrite next step

        // ---- chip-wide barrier ----
        if (tid == 0) {
            __threadfence();
            atomicAdd(&g_bar, 1u);
            const unsigned target = (unsigned)gridDim.x * (unsigned)(t + 1);
            while (ld_vol(&g_bar) < target) { }
            __threadfence();
        }
        __syncthreads();   // release CTA; protects h_s reuse next step
    }
}

// ---------------------------------------------------------------------
extern "C" void kernel_launch(void* const* d_in, const int* in_sizes, int n_in,
                              void* d_out, int out_size)
{
    const float* x  = (const float*)d_in[0];
    const float* z  = (const float*)d_in[1];
    const float* h0 = (const float*)d_in[2];
    const float* Wx = (const float*)d_in[3];
    const float* Wh = (const float*)d_in[4];
    const float* b  = (const float*)d_in[5];
    const float* gz = (const float*)d_in[6];
    const float* gh = (const float*)d_in[7];
    const float* bg = (const float*)d_in[8];

    float* out  = (float*)d_out;                       // [T,B,D]
    float* hout = out + (size_t)T_STEPS * BD;          // [T+1,B,D]

    init_kernel<<<1, 1>>>();

    dim3 gGemm(1024 / 64, (T_STEPS * B_SZ) / 64);      // (16, 512)
    xp_gemm_kernel<<<gGemm, 256>>>(x, Wx, b);

    const int smem_bytes = (16 * HP + 256 * RP) * (int)sizeof(float);  // 94208
    cudaFuncSetAttribute(recur_kernel,
                         cudaFuncAttributeMaxDynamicSharedMemorySize, smem_bytes);
    recur_kernel<<<NCTA, NTHR, smem_bytes>>>(z, h0, Wh, gz, gh, bg, out, hout);
}

// round 4
// speedup vs baseline: 1.7465x; 1.0715x over previous
#include <cuda_runtime.h>
#include <cstdint>

#define T_STEPS 2048
#define B_SZ    16
#define D_SZ    1024
#define BD      (B_SZ*D_SZ)          /* 16384 */
#define NCTA    128
#define NTHR    256
#define CLUSTER 4
#define SLICE_B 16384                /* 4 b-rows * 4KB, per-CTA bulk slice */
#define HBUF    16384                /* floats per h buffer */
#define RPITCH  20                   /* reduce row pitch (16 + 4, 16B-aligned) */

// 128 MB scratch for the precomputed input projection (allowed: __device__ global)
__device__ float    g_xp[(size_t)T_STEPS * BD];
__device__ unsigned g_bar;

// ---------------- packed fp32x2 helpers (sm_100+ PTX) ----------------
__device__ __forceinline__ void ffma2(unsigned long long &d,
                                      unsigned long long a,
                                      unsigned long long b) {
    asm("fma.rn.f32x2 %0, %1, %2, %0;" : "+l"(d) : "l"(a), "l"(b));
}
__device__ __forceinline__ unsigned long long dup2(float a) {
    unsigned long long r;
    asm("mov.b64 %0, {%1, %1};" : "=l"(r) : "f"(a));
    return r;
}
__device__ __forceinline__ float2 unpack2(unsigned long long v) {
    float2 r;
    asm("mov.b64 {%0, %1}, %2;" : "=f"(r.x), "=f"(r.y) : "l"(v));
    return r;
}

// ---------------- sync primitives ----------------
__device__ __forceinline__ unsigned ld_acq(const unsigned* p) {
    unsigned v;
    asm volatile("ld.acquire.gpu.global.u32 %0, [%1];" : "=r"(v) : "l"(p) : "memory");
    return v;
}
__device__ __forceinline__ void red_rel(unsigned* p) {
    asm volatile("red.add.release.gpu.global.u32 [%0], 1;" :: "l"(p) : "memory");
}
__device__ __forceinline__ void mbar_init(uint32_t mb, unsigned cnt) {
    asm volatile("mbarrier.init.shared.b64 [%0], %1;" :: "r"(mb), "r"(cnt) : "memory");
}
__device__ __forceinline__ void mbar_expect_tx(uint32_t mb, unsigned bytes) {
    asm volatile("mbarrier.arrive.expect_tx.shared.b64 _, [%0], %1;"
                 :: "r"(mb), "r"(bytes) : "memory");
}
__device__ __forceinline__ void mbar_wait(uint32_t mb, unsigned parity) {
    asm volatile(
        "{\n\t.reg .pred P;\n"
        "WAITLOOP_%=:\n\t"
        "mbarrier.try_wait.parity.acquire.cta.shared::cta.b64 P, [%0], %1, 0x989680;\n\t"
        "@!P bra WAITLOOP_%=;\n\t}"
        :: "r"(mb), "r"(parity) : "memory");
}
__device__ __forceinline__ void bulk_mc(uint32_t dst, const void* src,
                                        unsigned bytes, uint32_t mb,
                                        unsigned short mask) {
    asm volatile(
        "cp.async.bulk.shared::cluster.global.mbarrier::complete_tx::bytes"
        ".multicast::cluster [%0], [%1], %2, [%3], %4;"
        :: "r"(dst), "l"(src), "r"(bytes), "r"(mb), "h"(mask) : "memory");
}
__device__ __forceinline__ void fence_proxy_async_all() {
    asm volatile("fence.proxy.async;" ::: "memory");
}
__device__ __forceinline__ unsigned cluster_rank() {
    unsigned r;
    asm("mov.u32 %0, %%cluster_ctarank;" : "=r"(r));
    return r;
}
__device__ __forceinline__ void cluster_sync_() {
    asm volatile("barrier.cluster.arrive.aligned;" ::: "memory");
    asm volatile("barrier.cluster.wait.aligned;" ::: "memory");
}

__global__ void init_kernel() { g_bar = 0u; }

// ---------------------------------------------------------------------
// Kernel 1: xp[m,e] = sum_d x[m,d]*Wx[e,d] + b[e]   (unchanged from R2)
// ---------------------------------------------------------------------
__global__ __launch_bounds__(256) void xp_gemm_kernel(
    const float* __restrict__ X,
    const float* __restrict__ Wx,
    const float* __restrict__ bias)
{
    __shared__ __align__(16) float As[16][68];
    __shared__ __align__(16) float Bs[16][68];

    const int tid   = threadIdx.x;
    const int mBase = blockIdx.y * 64;
    const int nBase = blockIdx.x * 64;

    const int lrow = tid >> 2;
    const int lk4  = (tid & 3) << 2;
    const int ty = tid >> 4;
    const int tx = tid & 15;

    unsigned long long acc[4][2];
#pragma unroll
    for (int i = 0; i < 4; i++) { acc[i][0] = 0ull; acc[i][1] = 0ull; }

    for (int k0 = 0; k0 < 1024; k0 += 16) {
        float4 av = *reinterpret_cast<const float4*>(
            &X[(size_t)(mBase + lrow) * 1024 + k0 + lk4]);
        float4 bv = *reinterpret_cast<const float4*>(
            &Wx[(size_t)(nBase + lrow) * 1024 + k0 + lk4]);
        As[lk4 + 0][lrow] = av.x; As[lk4 + 1][lrow] = av.y;
        As[lk4 + 2][lrow] = av.z; As[lk4 + 3][lrow] = av.w;
        Bs[lk4 + 0][lrow] = bv.x; Bs[lk4 + 1][lrow] = bv.y;
        Bs[lk4 + 2][lrow] = bv.z; Bs[lk4 + 3][lrow] = bv.w;
        __syncthreads();

#pragma unroll
        for (int k = 0; k < 16; k++) {
            float4 a = *reinterpret_cast<const float4*>(&As[k][ty << 2]);
            ulonglong2 bp = *reinterpret_cast<const ulonglong2*>(&Bs[k][tx << 2]);
            unsigned long long a0 = dup2(a.x), a1 = dup2(a.y);
            unsigned long long a2 = dup2(a.z), a3 = dup2(a.w);
            ffma2(acc[0][0], a0, bp.x); ffma2(acc[0][1], a0, bp.y);
            ffma2(acc[1][0], a1, bp.x); ffma2(acc[1][1], a1, bp.y);
            ffma2(acc[2][0], a2, bp.x); ffma2(acc[2][1], a2, bp.y);
            ffma2(acc[3][0], a3, bp.x); ffma2(acc[3][1], a3, bp.y);
        }
        __syncthreads();
    }

    const int col = nBase + (tx << 2);
    const float4 bv = *reinterpret_cast<const float4*>(&bias[col]);
#pragma unroll
    for (int m = 0; m < 4; m++) {
        const int row = mBase + (ty << 2) + m;
        float2 c01 = unpack2(acc[m][0]);
        float2 c23 = unpack2(acc[m][1]);
        float4 r;
        r.x = c01.x + bv.x; r.y = c01.y + bv.y;
        r.z = c23.x + bv.z; r.w = c23.y + bv.w;
        *reinterpret_cast<float4*>(&g_xp[(size_t)row * 1024 + col]) = r;
    }
}

// ---------------------------------------------------------------------
// Kernel 2: persistent recurrence.
// 128 CTAs (32 clusters of 4) x 256 threads. CTA owns 8 columns; W_h in
// registers. Per step: each CTA bulk-multicasts a distinct 16KB quarter
// of h[t] to all 4 cluster CTAs (2MB/step chip L2 reads instead of 8MB).
// mbarrier (phase parity = t&1) gates compute; h double-buffered.
// Partials reduced via shfl then small SMEM buffer. Chip-wide barrier:
// red.add.release + ld.acquire poll by tid0 only.
// ---------------------------------------------------------------------
__global__ __launch_bounds__(256, 1) __cluster_dims__(CLUSTER, 1, 1)
void recur_kernel(
    const float* __restrict__ Z,
    const float* __restrict__ H0,
    const float* __restrict__ Wh,
    const float* __restrict__ Gz,
    const float* __restrict__ Gh,
    const float* __restrict__ Bg,
    float* __restrict__ Out,
    float* __restrict__ Hout)
{
    extern __shared__ __align__(1024) float sm[];
    float* h_s = sm;                         // 2 * 16384 floats
    float* red = sm + 2 * HBUF;              // 64 * RPITCH floats
    const uint32_t mb = (uint32_t)__cvta_generic_to_shared(red + 64 * RPITCH);

    const int tid  = threadIdx.x;
    const int warp = tid >> 5;
    const int lane = tid & 31;
    const int cta  = blockIdx.x;
    const unsigned rank = cluster_rank();

    const int n = lane & 7;          // column within CTA
    const int g = lane >> 3;         // k-subgroup 0..3
    const int gcol  = cta * 8 + n;
    const int kbase = warp * 128 + g * 32;

    // ---- mbarrier init (once) ----
    if (tid == 0) mbar_init(mb, 1);
    __syncthreads();
    if (tid == 0) fence_proxy_async_all();
    cluster_sync_();

    // ---- W_h slice -> registers (rotated k order: slot ii holds i=(ii+2g)&7) ----
    unsigned long long wA[8], wB[8];
    int off[8];
#pragma unroll
    for (int ii = 0; ii < 8; ii++) {
        const int i = (ii + 2 * g) & 7;
        off[ii] = i * 4;
        ulonglong2 v = *reinterpret_cast<const ulonglong2*>(
            Wh + (size_t)gcol * 1024 + kbase + i * 4);
        wA[ii] = v.x; wB[ii] = v.y;
    }

    // ---- epilogue role (threads 0..127): one output (b,n) each ----
    const int eb = tid >> 3;
    const int en = tid & 7;
    const int egcol = cta * 8 + en;
    float gz_r = 0.f, gh_r = 0.f, bg_r = 0.f;
    if (tid < 128) {
        gz_r = Gz[egcol]; gh_r = Gh[egcol]; bg_r = Bg[egcol];
        // h[0] = h0 (required output row 0; also the t=0 bulk source)
        Hout[(size_t)eb * 1024 + egcol] = H0[(size_t)eb * 1024 + egcol];
    }
    __syncthreads();

    // ---- pre-loop global barrier: Hout[0] visible chip-wide ----
    if (tid == 0) {
        red_rel(&g_bar);
        while (ld_acq(&g_bar) < (unsigned)NCTA) { }
        fence_proxy_async_all();
    }

    const uint32_t h_s_sh = (uint32_t)__cvta_generic_to_shared(h_s);

    for (int t = 0; t < T_STEPS; ++t) {
        const int buf = t & 1;

        // ---- cooperative-slice multicast load of h[t] ----
        if (tid == 0) {
            mbar_expect_tx(mb, 4 * SLICE_B);
            bulk_mc(h_s_sh + (uint32_t)(buf * HBUF * 4 + rank * SLICE_B),
                    Hout + (size_t)t * BD + rank * (SLICE_B / 4),
                    SLICE_B, mb, (unsigned short)0xF);
        }

        // ---- prefetch epilogue operands (independent of h) ----
        float xpv = 0.f, zv = 0.f;
        size_t eidx = 0;
        if (tid < 128) {
            eidx = (size_t)t * BD + (size_t)eb * 1024 + egcol;
            xpv = __ldcg(&g_xp[eidx]);
            zv  = __ldcg(&Z[eidx]);
        }

        mbar_wait(mb, (unsigned)buf);

        // ---- dot products: 512 MACs/thread, bank-conflict-free via rotation ----
        const float* hb = h_s + buf * HBUF + kbase;
        unsigned long long accA[16], accB[16];
#pragma unroll
        for (int b = 0; b < 16; b++) { accA[b] = 0ull; accB[b] = 0ull; }
#pragma unroll
        for (int ii = 0; ii < 8; ii++) {
            const float* hp = hb + off[ii];
#pragma unroll
            for (int b = 0; b < 16; b++) {
                ulonglong2 hv = *reinterpret_cast<const ulonglong2*>(hp + b * 1024);
                ffma2(accA[b], hv.x, wA[ii]);
                ffma2(accB[b], hv.y, wB[ii]);
            }
        }

        // ---- intra-warp reduce across g (4 partials -> 1) ----
        float s[16];
#pragma unroll
        for (int b = 0; b < 16; b++) {
            float2 a = unpack2(accA[b]);
            float2 c = unpack2(accB[b]);
            s[b] = (a.x + a.y) + (c.x + c.y);
            s[b] += __shfl_xor_sync(0xffffffffu, s[b], 8);
            s[b] += __shfl_xor_sync(0xffffffffu, s[b], 16);
        }
        if (lane < 8) {
            float* rp = red + (warp * 8 + lane) * RPITCH;
            *reinterpret_cast<float4*>(rp + 0)  = make_float4(s[0],  s[1],  s[2],  s[3]);
            *reinterpret_cast<float4*>(rp + 4)  = make_float4(s[4],  s[5],  s[6],  s[7]);
            *reinterpret_cast<float4*>(rp + 8)  = make_float4(s[8],  s[9],  s[10], s[11]);
            *reinterpret_cast<float4*>(rp + 12) = make_float4(s[12], s[13], s[14], s[15]);
        }
        __syncthreads();

        // ---- final reduce (8 partials) + h store ----
        float hn = 0.f, pre = 0.f;
        if (tid < 128) {
            float dot = 0.f;
#pragma unroll
            for (int w = 0; w < 8; w++)
                dot += red[(w * 8 + en) * RPITCH + eb];
            hn  = tanhf(xpv + dot);
            __stcg(&Hout[(size_t)(t + 1) * BD + (size_t)eb * 1024 + egcol], hn);
            pre = zv * gz_r + hn * gh_r + bg_r;
        }
        __syncthreads();   // all Hout stores issued before release

        if (tid == 0) red_rel(&g_bar);

        // ---- gate + Out store: off the critical path (after arrive) ----
        if (tid < 128) {
            const float sg = 1.0f / (1.0f + __expf(-pre));
            __stcg(&Out[eidx], hn * (pre * sg));
        }

        if (tid == 0) {
            const unsigned target = (unsigned)NCTA * (unsigned)(t + 2);
            while (ld_acq(&g_bar) < target) { }
            fence_proxy_async_all();
        }
        // non-tid0 threads flow to next mbar_wait (data-driven)
    }
}

// ---------------------------------------------------------------------
extern "C" void kernel_launch(void* const* d_in, const int* in_sizes, int n_in,
                              void* d_out, int out_size)
{
    const float* x  = (const float*)d_in[0];
    const float* z  = (const float*)d_in[1];
    const float* h0 = (const float*)d_in[2];
    const float* Wx = (const float*)d_in[3];
    const float* Wh = (const float*)d_in[4];
    const float* b  = (const float*)d_in[5];
    const float* gz = (const float*)d_in[6];
    const float* gh = (const float*)d_in[7];
    const float* bg = (const float*)d_in[8];

    float* out  = (float*)d_out;                       // [T,B,D]
    float* hout = out + (size_t)T_STEPS * BD;          // [T+1,B,D]

    init_kernel<<<1, 1>>>();

    dim3 gGemm(1024 / 64, (T_STEPS * B_SZ) / 64);      // (16, 512)
    xp_gemm_kernel<<<gGemm, 256>>>(x, Wx, b);

    const int smem_bytes = (2 * HBUF + 64 * RPITCH) * (int)sizeof(float) + 16;
    cudaFuncSetAttribute(recur_kernel,
                         cudaFuncAttributeMaxDynamicSharedMemorySize, smem_bytes);
    recur_kernel<<<NCTA, NTHR, smem_bytes>>>(z, h0, Wh, gz, gh, bg, out, hout);
}

// round 6
// speedup vs baseline: 1.9505x; 1.1168x over previous
#include <cuda_runtime.h>
#include <cstdint>

#define T_STEPS 2048
#define B_SZ    16
#define D_SZ    1024
#define BD      (B_SZ*D_SZ)          /* 16384 */
#define NCTA    128
#define NTHR    256
#define HROWP   1088                 /* h_s b-row pitch: 16 chunks * (64+4) */
#define RPITCH  12                   /* reduce row pitch (8 + 4) */

// 128 MB scratch for the precomputed input projection (allowed: __device__ global)
__device__ float    g_xp[(size_t)T_STEPS * BD];
__device__ unsigned g_bar;

// ---------------- packed fp32x2 helpers (sm_100+ PTX) ----------------
__device__ __forceinline__ void ffma2(unsigned long long &d,
                                      unsigned long long a,
                                      unsigned long long b) {
    asm("fma.rn.f32x2 %0, %1, %2, %0;" : "+l"(d) : "l"(a), "l"(b));
}
__device__ __forceinline__ unsigned long long dup2(float a) {
    unsigned long long r;
    asm("mov.b64 %0, {%1, %1};" : "=l"(r) : "f"(a));
    return r;
}
__device__ __forceinline__ float2 unpack2(unsigned long long v) {
    float2 r;
    asm("mov.b64 {%0, %1}, %2;" : "=f"(r.x), "=f"(r.y) : "l"(v));
    return r;
}
__device__ __forceinline__ void cp16(uint32_t dst_smem, const void* src) {
    asm volatile("cp.async.cg.shared.global [%0], [%1], 16;"
                 :: "r"(dst_smem), "l"(src) : "memory");
}
#define CP_COMMIT() asm volatile("cp.async.commit_group;" ::: "memory")
#define CP_WAIT(N)  asm volatile("cp.async.wait_group %0;" :: "n"(N) : "memory")

// ---------------- sync primitives (proven in R3) ----------------
__device__ __forceinline__ unsigned ld_acq(const unsigned* p) {
    unsigned v;
    asm volatile("ld.acquire.gpu.global.u32 %0, [%1];" : "=r"(v) : "l"(p) : "memory");
    return v;
}
__device__ __forceinline__ void red_rel(unsigned* p) {
    asm volatile("red.add.release.gpu.global.u32 [%0], 1;" :: "l"(p) : "memory");
}

__global__ void init_kernel() { g_bar = 0u; }
__global__ void dummy_kernel() { }   // launch-index padding so ncu -s 5 hits recur

// ---------------------------------------------------------------------
// Kernel 1: xp[m,e] = sum_d x[m,d]*Wx[e,d] + b[e]   (unchanged)
// ---------------------------------------------------------------------
__global__ __launch_bounds__(256) void xp_gemm_kernel(
    const float* __restrict__ X,
    const float* __restrict__ Wx,
    const float* __restrict__ bias)
{
    __shared__ __align__(16) float As[16][68];
    __shared__ __align__(16) float Bs[16][68];

    const int tid   = threadIdx.x;
    const int mBase = blockIdx.y * 64;
    const int nBase = blockIdx.x * 64;

    const int lrow = tid >> 2;
    const int lk4  = (tid & 3) << 2;
    const int ty = tid >> 4;
    const int tx = tid & 15;

    unsigned long long acc[4][2];
#pragma unroll
    for (int i = 0; i < 4; i++) { acc[i][0] = 0ull; acc[i][1] = 0ull; }

    for (int k0 = 0; k0 < 1024; k0 += 16) {
        float4 av = *reinterpret_cast<const float4*>(
            &X[(size_t)(mBase + lrow) * 1024 + k0 + lk4]);
        float4 bv = *reinterpret_cast<const float4*>(
            &Wx[(size_t)(nBase + lrow) * 1024 + k0 + lk4]);
        As[lk4 + 0][lrow] = av.x; As[lk4 + 1][lrow] = av.y;
        As[lk4 + 2][lrow] = av.z; As[lk4 + 3][lrow] = av.w;
        Bs[lk4 + 0][lrow] = bv.x; Bs[lk4 + 1][lrow] = bv.y;
        Bs[lk4 + 2][lrow] = bv.z; Bs[lk4 + 3][lrow] = bv.w;
        __syncthreads();

#pragma unroll
        for (int k = 0; k < 16; k++) {
            float4 a = *reinterpret_cast<const float4*>(&As[k][ty << 2]);
            ulonglong2 bp = *reinterpret_cast<const ulonglong2*>(&Bs[k][tx << 2]);
            unsigned long long a0 = dup2(a.x), a1 = dup2(a.y);
            unsigned long long a2 = dup2(a.z), a3 = dup2(a.w);
            ffma2(acc[0][0], a0, bp.x); ffma2(acc[0][1], a0, bp.y);
            ffma2(acc[1][0], a1, bp.x); ffma2(acc[1][1], a1, bp.y);
            ffma2(acc[2][0], a2, bp.x); ffma2(acc[2][1], a2, bp.y);
            ffma2(acc[3][0], a3, bp.x); ffma2(acc[3][1], a3, bp.y);
        }
        __syncthreads();
    }

    const int col = nBase + (tx << 2);
    const float4 bv = *reinterpret_cast<const float4*>(&bias[col]);
#pragma unroll
    for (int m = 0; m < 4; m++) {
        const int row = mBase + (ty << 2) + m;
        float2 c01 = unpack2(acc[m][0]);
        float2 c23 = unpack2(acc[m][1]);
        float4 r;
        r.x = c01.x + bv.x; r.y = c01.y + bv.y;
        r.z = c23.x + bv.z; r.w = c23.y + bv.w;
        *reinterpret_cast<float4*>(&g_xp[(size_t)row * 1024 + col]) = r;
    }
}

// ---------------------------------------------------------------------
// Kernel 2: persistent recurrence, batch-split tiling. NO clusters.
// 128 CTAs x 256 threads. CTA = (bg = cta&1 -> 8 b-rows, ng = cta>>1 ->
// 16 columns). Per step each CTA cp.asyncs only ITS 8 b-rows of h[t]
// (32KB; chip total 4MB/step) in 4 per-b-pair commit groups, computing
// each b-pair as its slice lands. W_h (16 cols x 64 k per thread's
// slice) register-resident. Chunk-padded h layout (64+4) => LDS.128
// conflict-free with 16-way lane broadcast. Chip barrier: red.release +
// ld.acquire poll by tid0 (proven R3).
// ---------------------------------------------------------------------
__global__ __launch_bounds__(256, 1) void recur_kernel(
    const float* __restrict__ Z,
    const float* __restrict__ H0,
    const float* __restrict__ Wh,
    const float* __restrict__ Gz,
    const float* __restrict__ Gh,
    const float* __restrict__ Bg,
    float* __restrict__ Out,
    float* __restrict__ Hout)
{
    extern __shared__ __align__(16) float sm[];
    float* h_s = sm;                      // 8 * HROWP floats (~34KB)
    float* red = sm + 8 * HROWP;          // 128 * RPITCH floats

    const int tid  = threadIdx.x;
    const int warp = tid >> 5;
    const int lane = tid & 31;
    const int cta  = blockIdx.x;

    const int bg    = cta & 1;            // batch group: rows bg*8..bg*8+7
    const int ng    = cta >> 1;           // column group: cols ng*16..+15
    const int bbase = bg * 8;

    const int n     = lane & 15;          // column within CTA (0..15)
    const int khalf = lane >> 4;          // 0/1
    const int ks    = warp * 2 + khalf;   // k-chunk 0..15 (64 k each)
    const int kbase = ks * 64;
    const int gcol  = ng * 16 + n;

    // ---- W_h slice (64 floats) -> registers, resident for all steps ----
    unsigned long long wx[16], wy[16];
    {
        const float* wp = Wh + (size_t)gcol * 1024 + kbase;
#pragma unroll
        for (int i = 0; i < 16; i++) {
            ulonglong2 v = *reinterpret_cast<const ulonglong2*>(wp + i * 4);
            wx[i] = v.x; wy[i] = v.y;
        }
    }

    // ---- staging assignment: 2 cp16 pieces per thread per b-pair group ----
    // piece p in [0,512): b_off = p>>8, f = (p&255)*4
    int dstoff[2], srcoff[2];
#pragma unroll
    for (int j = 0; j < 2; j++) {
        const int p    = tid + 256 * j;
        const int boff = p >> 8;
        const int f    = (p & 255) * 4;
        dstoff[j] = boff * HROWP + (f >> 6) * 68 + (f & 63);
        srcoff[j] = boff * 1024 + f;
    }
    const uint32_t h_sh = (uint32_t)__cvta_generic_to_shared(h_s);

    // ---- epilogue role (threads 0..127): one output (b,n) each ----
    const int eb  = tid >> 4;             // local b 0..7
    const int en  = tid & 15;             // local n 0..15
    const int egb = bbase + eb;           // global b
    const int egc = ng * 16 + en;         // global col
    float gz_r = 0.f, gh_r = 0.f, bg_r = 0.f;
    if (tid < 128) {
        gz_r = Gz[egc]; gh_r = Gh[egc]; bg_r = Bg[egc];
        // h[0] = h0 (required output row 0; also the t=0 staging source)
        Hout[(size_t)egb * 1024 + egc] = H0[(size_t)egb * 1024 + egc];
    }
    __syncthreads();

    // ---- pre-loop global barrier: Hout[0] visible chip-wide ----
    if (tid == 0) {
        red_rel(&g_bar);
        while (ld_acq(&g_bar) < (unsigned)NCTA) { }
    }
    __syncthreads();

    for (int t = 0; t < T_STEPS; ++t) {
        // ---- stage this CTA's 8 b-rows of h[t]: 4 groups of 2 rows ----
        const float* hrow = Hout + (size_t)t * BD + (size_t)bbase * 1024;
#pragma unroll
        for (int s = 0; s < 4; s++) {
            const float* gsrc = hrow + s * 2048;
            const uint32_t gdst = h_sh + (uint32_t)(s * 2 * HROWP) * 4u;
            cp16(gdst + (uint32_t)dstoff[0] * 4u, gsrc + srcoff[0]);
            cp16(gdst + (uint32_t)dstoff[1] * 4u, gsrc + srcoff[1]);
            CP_COMMIT();
        }

        // ---- prefetch epilogue operands (independent of h) ----
        float xpv = 0.f, zv = 0.f;
        size_t eidx = 0;
        if (tid < 128) {
            eidx = (size_t)t * BD + (size_t)egb * 1024 + egc;
            xpv = __ldcg(&g_xp[eidx]);
            zv  = __ldcg(&Z[eidx]);
        }

        // ---- slice-pipelined dot products (b-pair per slice) ----
        unsigned long long accA[8], accB[8];
#pragma unroll
        for (int b = 0; b < 8; b++) { accA[b] = 0ull; accB[b] = 0ull; }
        const float* hc = h_s + ks * 68;   // this thread's chunk base

#define COMPUTE_PAIR(S)                                                      \
        do {                                                                 \
            __syncthreads();                                                 \
            _Pragma("unroll")                                                \
            for (int i = 0; i < 16; i++) {                                   \
                ulonglong2 h0v = *reinterpret_cast<const ulonglong2*>(       \
                    hc + (2*(S)) * HROWP + i * 4);                           \
                ffma2(accA[2*(S)],   h0v.x, wx[i]);                          \
                ffma2(accB[2*(S)],   h0v.y, wy[i]);                          \
                ulonglong2 h1v = *reinterpret_cast<const ulonglong2*>(       \
                    hc + (2*(S)+1) * HROWP + i * 4);                         \
                ffma2(accA[2*(S)+1], h1v.x, wx[i]);                          \
                ffma2(accB[2*(S)+1], h1v.y, wy[i]);                          \
            }                                                                \
        } while (0)

        CP_WAIT(3); COMPUTE_PAIR(0);
        CP_WAIT(2); COMPUTE_PAIR(1);
        CP_WAIT(1); COMPUTE_PAIR(2);
        CP_WAIT(0); COMPUTE_PAIR(3);
#undef COMPUTE_PAIR

        // ---- reduce: khalf pair via shfl, then 8 warps via SMEM ----
        float s8[8];
#pragma unroll
        for (int b = 0; b < 8; b++) {
            float2 a = unpack2(accA[b]);
            float2 c = unpack2(accB[b]);
            s8[b] = (a.x + a.y) + (c.x + c.y);
            s8[b] += __shfl_xor_sync(0xffffffffu, s8[b], 16);
        }
        if (lane < 16) {
            float* rp = red + (warp * 16 + n) * RPITCH;
            *reinterpret_cast<float4*>(rp + 0) = make_float4(s8[0], s8[1], s8[2], s8[3]);
            *reinterpret_cast<float4*>(rp + 4) = make_float4(s8[4], s8[5], s8[6], s8[7]);
        }
        __syncthreads();

        // ---- final reduce (8 warp-partials) + h store ----
        float hn = 0.f, pre = 0.f;
        if (tid < 128) {
            float dot = 0.f;
#pragma unroll
            for (int w = 0; w < 8; w++)
                dot += red[(w * 16 + en) * RPITCH + eb];
            hn  = tanhf(xpv + dot);
            __stcg(&Hout[(size_t)(t + 1) * BD + (size_t)egb * 1024 + egc], hn);
            pre = zv * gz_r + hn * gh_r + bg_r;
        }
        __syncthreads();   // Hout stores issued (+ red safe) before release

        if (tid == 0) red_rel(&g_bar);

        // ---- gate + Out store: off the critical path (after arrive) ----
        if (tid < 128) {
            const float sg = 1.0f / (1.0f + __expf(-pre));
            __stcg(&Out[eidx], hn * (pre * sg));
        }

        if (tid == 0) {
            const unsigned target = (unsigned)NCTA * (unsigned)(t + 2);
            while (ld_acq(&g_bar) < target) { }
        }
        __syncthreads();   // release all threads before next staging
    }
}

// ---------------------------------------------------------------------
extern "C" void kernel_launch(void* const* d_in, const int* in_sizes, int n_in,
                              void* d_out, int out_size)
{
    const float* x  = (const float*)d_in[0];
    const float* z  = (const float*)d_in[1];
    const float* h0 = (const float*)d_in[2];
    const float* Wx = (const float*)d_in[3];
    const float* Wh = (const float*)d_in[4];
    const float* b  = (const float*)d_in[5];
    const float* gz = (const float*)d_in[6];
    const float* gh = (const float*)d_in[7];
    const float* bg = (const float*)d_in[8];

    float* out  = (float*)d_out;                       // [T,B,D]
    float* hout = out + (size_t)T_STEPS * BD;          // [T+1,B,D]

    init_kernel<<<1, 1>>>();
    // padding so ncu (-s 5 -c 1) captures recur_kernel
    dummy_kernel<<<1, 1>>>();
    dummy_kernel<<<1, 1>>>();
    dummy_kernel<<<1, 1>>>();

    dim3 gGemm(1024 / 64, (T_STEPS * B_SZ) / 64);      // (16, 512)
    xp_gemm_kernel<<<gGemm, 256>>>(x, Wx, b);

    // actual need ~41KB; pad to force 1 CTA/SM so the grid barrier never
    // waits on two co-resident CTAs sharing one SM's FMA pipes.
    const int smem_bytes = 118784;
    cudaFuncSetAttribute(recur_kernel,
                         cudaFuncAttributeMaxDynamicSharedMemorySize, smem_bytes);
    recur_kernel<<<NCTA, NTHR, smem_bytes>>>(z, h0, Wh, gz, gh, bg, out, hout);
}